// round 13
// baseline (speedup 1.0000x reference)
#include <cuda_runtime.h>

// Problem constants (fixed by the reference)
constexpr int B  = 8;
constexpr int C  = 256;
constexpr int H  = 64;
constexpr int W  = 64;
constexpr int WC = 16;           // weight channels
constexpr int G  = C / WC;       // 16 groups sharing each weight
constexpr int HW = H * W;        // 4096
constexpr int Q  = HW / 4;       // float4 quads per plane = 1024
constexpr int GSTRIDE = WC * HW; // plane stride between groups (65536 floats)

// Lane-pair row split: even lane = output row oh (loads x rows oh-1, oh),
// odd lane = output row oh+1 (loads rows oh+1, oh+2). Middle rows are
// exchanged via shfl_xor(1). A warp covers one 64-wide row-pair
// (lane = qcol*2 + sub), so horizontal neighbors are at lane +/-2.
// Per-thread weights: 9 float4 (36 regs) -> ~70 regs total ->
// 7 CTAs x 128 thr/SM = 28 warps/SM, single wave (1024 CTAs <= 1036).
__global__ __launch_bounds__(128, 7) void agg_kernel_v10(
    const float* __restrict__ x,
    const float* __restrict__ w,
    float* __restrict__ out)
{
    const int idx  = blockIdx.x * 128 + threadIdx.x;  // 0 .. 131071
    const int sub  = idx & 1;              // 0: top row, 1: bottom row
    const int qcol = (idx >> 1) & 15;      // quad column (16 per row)
    const int rp   = (idx >> 5) & 31;      // row pair
    const int wc   = (idx >> 10) & (WC - 1);
    const int b    = idx >> 14;

    const int oh   = rp << 1;              // even output row of the pair
    const int own  = oh + sub;             // this thread's output row
    const int base = oh - 1 + 2 * sub;     // first x row this thread loads

    const bool v0 = (base >= 0);           // x row `base`   in range
    const bool v1 = (base <= H - 2);       // x row `base+1` in range
    const float mL = (qcol == 0)  ? 0.f : 1.f;
    const float mR = (qcol == 15) ? 0.f : 1.f;

    // 9 weight float4s for this thread's output row.
    const float4* wp = (const float4*)(w + ((size_t)(b * WC + wc) * 9) * HW
                                         + own * W + qcol * 4);
    float4 wv[9];
    #pragma unroll
    for (int t = 0; t < 9; t++) wv[t] = wp[(size_t)t * Q];

    // x pointer at row `base` (may be row -1; loads are predicated, so the
    // invalid address is never dereferenced and the +W offset stays correct).
    const float* xc = x   + (size_t)(b * C + wc) * HW + base * W + qcol * 4;
    float*       op = out + (size_t)(b * C + wc) * HW + own  * W + qcol * 4;

    const float4 z4 = make_float4(0.f, 0.f, 0.f, 0.f);

    auto ld2 = [&](float4& a, float4& bb, const float* p) {
        a  = v0 ? *(const float4*)(p)     : z4;
        bb = v1 ? *(const float4*)(p + W) : z4;
    };

    float4 c0, c1, n0, n1;
    ld2(c0, c1, xc);

    #pragma unroll
    for (int g = 0; g < G; g++) {
        // Prefetch next group's two rows.
        xc += GSTRIDE;
        if (g < G - 1) ld2(n0, n1, xc);

        // Exchange the middle rows with the partner lane:
        // even sends c1 (row oh), odd sends c0 (row oh+1).
        float4 send = sub ? c0 : c1;
        float4 recv;
        recv.x = __shfl_xor_sync(0xffffffffu, send.x, 1);
        recv.y = __shfl_xor_sync(0xffffffffu, send.y, 1);
        recv.z = __shfl_xor_sync(0xffffffffu, send.z, 1);
        recv.w = __shfl_xor_sync(0xffffffffu, send.w, 1);

        // Stencil rows for this thread's output row.
        const float4 top = sub ? recv : c0;
        const float4 mid = sub ? c0   : c1;
        const float4 bot = sub ? c1   : recv;

        float4 acc = z4;
        const float4 rows[3] = { top, mid, bot };
        #pragma unroll
        for (int r = 0; r < 3; r++) {
            const float4 cc = rows[r];
            // Horizontal neighbors live 2 lanes away (same row, qcol +/- 1).
            const float lf = __shfl_up_sync  (0xffffffffu, cc.w, 2) * mL;
            const float rt = __shfl_down_sync(0xffffffffu, cc.x, 2) * mR;

            const float4 wl = wv[3 * r + 0];
            const float4 wm = wv[3 * r + 1];
            const float4 wr = wv[3 * r + 2];

            acc.x += lf   * wl.x + cc.x * wm.x + cc.y * wr.x;
            acc.y += cc.x * wl.y + cc.y * wm.y + cc.z * wr.y;
            acc.z += cc.y * wl.z + cc.z * wm.z + cc.w * wr.z;
            acc.w += cc.z * wl.w + cc.w * wm.w + rt   * wr.w;
        }

        *(float4*)(op) = acc;
        op += GSTRIDE;

        c0 = n0;
        c1 = n1;
    }
}

extern "C" void kernel_launch(void* const* d_in, const int* in_sizes, int n_in,
                              void* d_out, int out_size)
{
    const float* x = (const float*)d_in[0];   // (8,256,64,64) f32
    const float* w = (const float*)d_in[1];   // (8,16,9,4096) f32
    float* out = (float*)d_out;               // (8,256,64,64) f32

    const int total = B * WC * Q;             // 131072 threads (1 row each)
    agg_kernel_v10<<<total / 128, 128>>>(x, w, out);
}

// round 14
// speedup vs baseline: 1.1609x; 1.1609x over previous
#include <cuda_runtime.h>

// Problem constants (fixed by the reference)
constexpr int B  = 8;
constexpr int C  = 256;
constexpr int H  = 64;
constexpr int W  = 64;
constexpr int WC = 16;           // weight channels
constexpr int G  = C / WC;       // 16 groups sharing each weight
constexpr int HW = H * W;        // 4096
constexpr int Q  = HW / 4;       // float4 quads per plane = 1024
constexpr int GSTRIDE = WC * HW; // plane stride between groups (65536 floats)

// One thread = one (b, wc, 2-row pair of quads) over all 16 groups.
// v6 structure, but ALL neighbor values (left/right scalars) are fetched as
// predicated LDG.32 inside the distance-1 prefetch bundle instead of via
// shuffles. The compute phase is pure FFMA + STG with no exposed latency.
__global__ __launch_bounds__(64, 7) void agg_kernel_v11(
    const float* __restrict__ x,
    const float* __restrict__ w,
    float* __restrict__ out)
{
    const int idx  = blockIdx.x * 64 + threadIdx.x;  // 0 .. 65535
    const int q2   = idx & 511;            // 32 row-pairs x 16 quad-cols
    const int wc   = (idx >> 9) & (WC - 1);
    const int b    = idx >> 13;
    const int qcol = q2 & 15;
    const int oh   = (q2 >> 4) << 1;       // even output row
    const int p4   = oh * W + qcol * 4;    // first pixel of top quad

    const bool ym = (oh > 0);              // x row oh-1 exists
    const bool yp = (oh < H - 2);          // x row oh+2 exists
    const bool hL = (qcol > 0);            // left neighbor exists
    const bool hR = (qcol < 15);           // right neighbor exists

    // Weights: 9 taps for output row oh (wv0) and row oh+1 (wv1).
    const float4* wp = (const float4*)(w + ((size_t)(b * WC + wc) * 9) * HW + p4);
    float4 wv0[9], wv1[9];
    #pragma unroll
    for (int t = 0; t < 9; t++) {
        wv0[t] = wp[(size_t)t * Q];
        wv1[t] = wp[(size_t)t * Q + 16];   // +64 floats = next row
    }

    const float* xc = x   + (size_t)(b * C + wc) * HW + p4;  // group-0 top quad
    float*       op = out + (size_t)(b * C + wc) * HW + p4;

    const float4 z4 = make_float4(0.f, 0.f, 0.f, 0.f);

    // Load one group's 4 rows plus their left/right scalar neighbors.
    // rows: oh-1, oh, oh+1, oh+2 (row 0 valid iff ym, row 3 valid iff yp).
    auto load_bundle = [&](float4* c, float* lf, float* rt, const float* p) {
        const bool rv[4] = { ym, true, true, yp };
        #pragma unroll
        for (int a = 0; a < 4; a++) {
            const float* r = p + (a - 1) * W;
            c[a]  = rv[a]       ? *(const float4*)(r) : z4;
            lf[a] = (rv[a] & hL) ? r[-1] : 0.f;
            rt[a] = (rv[a] & hR) ? r[4]  : 0.f;
        }
    };

    float4 cb0[4], cb1[4];
    float  lf0[4], lf1[4], rt0[4], rt1[4];
    load_bundle(cb0, lf0, rt0, xc);

    #pragma unroll
    for (int g = 0; g < G; g++) {
        float4* c  = (g & 1) ? cb1 : cb0;
        float*  lf = (g & 1) ? lf1 : lf0;
        float*  rt = (g & 1) ? rt1 : rt0;
        float4* nc = (g & 1) ? cb0 : cb1;
        float*  nl = (g & 1) ? lf0 : lf1;
        float*  nr = (g & 1) ? rt0 : rt1;

        // Prefetch next group's bundle before computing this one.
        xc += GSTRIDE;
        if (g < G - 1) load_bundle(nc, nl, nr, xc);

        float4 acc0 = z4, acc1 = z4;

        #pragma unroll
        for (int a = 0; a < 4; a++) {
            const float4 cc = c[a];
            const float  l  = lf[a];
            const float  r  = rt[a];

            if (a < 3) {   // contributes to output row oh via tap row a
                const float4 wl = wv0[3 * a + 0];
                const float4 wm = wv0[3 * a + 1];
                const float4 wr = wv0[3 * a + 2];
                acc0.x += l    * wl.x + cc.x * wm.x + cc.y * wr.x;
                acc0.y += cc.x * wl.y + cc.y * wm.y + cc.z * wr.y;
                acc0.z += cc.y * wl.z + cc.z * wm.z + cc.w * wr.z;
                acc0.w += cc.z * wl.w + cc.w * wm.w + r    * wr.w;
            }
            if (a > 0) {   // contributes to output row oh+1 via tap row a-1
                const float4 wl = wv1[3 * (a - 1) + 0];
                const float4 wm = wv1[3 * (a - 1) + 1];
                const float4 wr = wv1[3 * (a - 1) + 2];
                acc1.x += l    * wl.x + cc.x * wm.x + cc.y * wr.x;
                acc1.y += cc.x * wl.y + cc.y * wm.y + cc.z * wr.y;
                acc1.z += cc.y * wl.z + cc.z * wm.z + cc.w * wr.z;
                acc1.w += cc.z * wl.w + cc.w * wm.w + r    * wr.w;
            }
        }

        *(float4*)(op)     = acc0;
        *(float4*)(op + W) = acc1;
        op += GSTRIDE;
    }
}

extern "C" void kernel_launch(void* const* d_in, const int* in_sizes, int n_in,
                              void* d_out, int out_size)
{
    const float* x = (const float*)d_in[0];   // (8,256,64,64) f32
    const float* w = (const float*)d_in[1];   // (8,16,9,4096) f32
    float* out = (float*)d_out;               // (8,256,64,64) f32

    const int total = B * WC * (Q / 2);       // 65536 threads (2 rows each)
    agg_kernel_v11<<<total / 64, 64>>>(x, w, out);
}

// round 15
// speedup vs baseline: 1.1893x; 1.0245x over previous
#include <cuda_runtime.h>
#include <cstdint>

// Problem constants (fixed by the reference)
constexpr int B  = 8;
constexpr int C  = 256;
constexpr int H  = 64;
constexpr int W  = 64;
constexpr int WC = 16;           // weight channels
constexpr int G  = C / WC;       // 16 groups sharing each weight
constexpr int HW = H * W;        // 4096
constexpr int Q  = HW / 4;       // float4 quads per plane = 1024
constexpr int GSTRIDE = WC * HW; // plane stride between groups (65536 floats)

__device__ __forceinline__ uint64_t pk(float lo, float hi) {
    uint64_t r;
    asm("mov.b64 %0, {%1, %2};" : "=l"(r) : "f"(lo), "f"(hi));
    return r;
}
__device__ __forceinline__ uint64_t fma2(uint64_t a, uint64_t b, uint64_t c) {
    uint64_t d;
    asm("fma.rn.f32x2 %0, %1, %2, %3;" : "=l"(d) : "l"(a), "l"(b), "l"(c));
    return d;
}
__device__ __forceinline__ float2 unpk(uint64_t v) {
    float lo, hi;
    asm("mov.b64 {%0, %1}, %2;" : "=f"(lo), "=f"(hi) : "l"(v));
    return make_float2(lo, hi);
}

// v6 structure (2-row vertical tile, 18 weight vectors register-resident,
// distance-1 prefetch, shuffles for horizontal neighbors) with the tap math
// executed as packed fma.rn.f32x2: 72 FFMA/group -> 36 FFMA2 + 12 packs.
__global__ __launch_bounds__(64, 7) void agg_kernel_v12(
    const float* __restrict__ x,
    const float* __restrict__ w,
    float* __restrict__ out)
{
    const int idx  = blockIdx.x * 64 + threadIdx.x;  // 0 .. 65535
    const int q2   = idx & 511;            // 32 row-pairs x 16 quad-cols
    const int wc   = (idx >> 9) & (WC - 1);
    const int b    = idx >> 13;
    const int qcol = q2 & 15;
    const int oh   = (q2 >> 4) << 1;       // even output row
    const int p4   = oh * W + qcol * 4;    // first pixel of top quad

    const float mL = (qcol == 0)  ? 0.f : 1.f;
    const float mR = (qcol == 15) ? 0.f : 1.f;
    const bool ym  = (oh > 0);             // x row oh-1 exists
    const bool yp  = (oh < H - 2);         // x row oh+2 exists

    // Weights for output rows oh (set 0) and oh+1 (set 1), packed as f32x2:
    // wpk[s][t][0] = (w.x, w.y), wpk[s][t][1] = (w.z, w.w).
    const float4* wp = (const float4*)(w + ((size_t)(b * WC + wc) * 9) * HW + p4);
    uint64_t wpk0[9][2], wpk1[9][2];
    #pragma unroll
    for (int t = 0; t < 9; t++) {
        const float4 a0 = wp[(size_t)t * Q];
        const float4 a1 = wp[(size_t)t * Q + 16];   // +64 floats = next row
        wpk0[t][0] = pk(a0.x, a0.y);  wpk0[t][1] = pk(a0.z, a0.w);
        wpk1[t][0] = pk(a1.x, a1.y);  wpk1[t][1] = pk(a1.z, a1.w);
    }

    const float* xc = x   + (size_t)(b * C + wc) * HW + p4;  // group-0 top quad
    float*       op = out + (size_t)(b * C + wc) * HW + p4;

    const float4 z4 = make_float4(0.f, 0.f, 0.f, 0.f);

    auto load_rows = [&](float4* c, const float* p) {
        c[0] = ym ? *(const float4*)(p - W)     : z4;
        c[1] =      *(const float4*)(p);
        c[2] =      *(const float4*)(p + W);
        c[3] = yp ? *(const float4*)(p + 2 * W) : z4;
    };

    float4 buf0[4], buf1[4];
    load_rows(buf0, xc);

    #pragma unroll
    for (int g = 0; g < G; g++) {
        float4* c = (g & 1) ? buf1 : buf0;
        float4* n = (g & 1) ? buf0 : buf1;

        // Prefetch next group's rows before computing this one.
        xc += GSTRIDE;
        if (g < G - 1) load_rows(n, xc);

        uint64_t a0xy = 0, a0zw = 0, a1xy = 0, a1zw = 0;  // 0 == (0.f,0.f)

        #pragma unroll
        for (int a = 0; a < 4; a++) {
            const float4 cc = c[a];
            const float lf = __shfl_up_sync  (0xffffffffu, cc.w, 1) * mL;
            const float rt = __shfl_down_sync(0xffffffffu, cc.x, 1) * mR;

            // Shifted data pairs (shared by both output rows).
            const uint64_t P0 = pk(lf,   cc.x);
            const uint64_t P1 = pk(cc.x, cc.y);
            const uint64_t P2 = pk(cc.y, cc.z);
            const uint64_t P3 = pk(cc.z, cc.w);
            const uint64_t P4 = pk(cc.w, rt);

            if (a < 3) {   // output row oh, tap row a
                a0xy = fma2(P0, wpk0[3 * a + 0][0], a0xy);
                a0xy = fma2(P1, wpk0[3 * a + 1][0], a0xy);
                a0xy = fma2(P2, wpk0[3 * a + 2][0], a0xy);
                a0zw = fma2(P2, wpk0[3 * a + 0][1], a0zw);
                a0zw = fma2(P3, wpk0[3 * a + 1][1], a0zw);
                a0zw = fma2(P4, wpk0[3 * a + 2][1], a0zw);
            }
            if (a > 0) {   // output row oh+1, tap row a-1
                a1xy = fma2(P0, wpk1[3 * (a - 1) + 0][0], a1xy);
                a1xy = fma2(P1, wpk1[3 * (a - 1) + 1][0], a1xy);
                a1xy = fma2(P2, wpk1[3 * (a - 1) + 2][0], a1xy);
                a1zw = fma2(P2, wpk1[3 * (a - 1) + 0][1], a1zw);
                a1zw = fma2(P3, wpk1[3 * (a - 1) + 1][1], a1zw);
                a1zw = fma2(P4, wpk1[3 * (a - 1) + 2][1], a1zw);
            }
        }

        const float2 r0 = unpk(a0xy), r1 = unpk(a0zw);
        const float2 r2 = unpk(a1xy), r3 = unpk(a1zw);
        *(float4*)(op)     = make_float4(r0.x, r0.y, r1.x, r1.y);
        *(float4*)(op + W) = make_float4(r2.x, r2.y, r3.x, r3.y);
        op += GSTRIDE;
    }
}

extern "C" void kernel_launch(void* const* d_in, const int* in_sizes, int n_in,
                              void* d_out, int out_size)
{
    const float* x = (const float*)d_in[0];   // (8,256,64,64) f32
    const float* w = (const float*)d_in[1];   // (8,16,9,4096) f32
    float* out = (float*)d_out;               // (8,256,64,64) f32

    const int total = B * WC * (Q / 2);       // 65536 threads (2 rows each)
    agg_kernel_v12<<<total / 64, 64>>>(x, w, out);
}